// round 12
// baseline (speedup 1.0000x reference)
#include <cuda_runtime.h>
#include <cstdint>

// Problem constants
#define T_TOK 32768      // B*S tokens
#define DDIM  512
#define EDIM  16
#define MDIM  1024
#define NROWS (T_TOK * 2)        // total (token,slot) rows = 65536
#define ROWS_PAD (NROWS + 128)
#define MAXTILES 528

typedef unsigned long long ull;

// ---------------- f32x2 packed-math helpers ----------------
__device__ __forceinline__ ull dup2(float v) {
    ull r; unsigned u = __float_as_uint(v);
    asm("mov.b64 %0, {%1, %1};" : "=l"(r) : "r"(u));
    return r;
}
__device__ __forceinline__ ull fma2(ull a, ull b, ull c) {
    ull d;
    asm("fma.rn.f32x2 %0, %1, %2, %3;" : "=l"(d) : "l"(a), "l"(b), "l"(c));
    return d;
}
__device__ __forceinline__ float2 unpack2(ull v) {
    unsigned lo, hi;
    asm("mov.b64 {%0, %1}, %2;" : "=r"(lo), "=r"(hi) : "l"(v));
    return make_float2(__uint_as_float(lo), __uint_as_float(hi));
}

// ---------------- device scratch (allocation-free) ----------------
__device__ float g_H[(size_t)ROWS_PAD * MDIM];   // gated hidden, gate folded in
__device__ int   g_cnt[EDIM];
__device__ int   g_off[EDIM];
__device__ int   g_cursor[EDIM];
__device__ int   g_list[NROWS];                  // packed token*2 + slot, per-expert segments
__device__ float g_gw[NROWS];                    // gate weight, indexed by token*2+slot
__device__ int   g_eidx[NROWS];                  // expert id, indexed by token*2+slot
__device__ int   g_tileE[MAXTILES];
__device__ int   g_tileR[MAXTILES];
__device__ int   g_nTiles;

// ---------------- kernel 0: zero counters ----------------
__global__ void init_kernel() {
    int i = threadIdx.x;
    if (i < EDIM) g_cnt[i] = 0;
}

// ---------------- kernel 1: routing (gate logits + top-2 + softmax) ----------------
__global__ void routing_kernel(const float* __restrict__ x, const float* __restrict__ wg) {
    __shared__ float wgT[EDIM][DDIM];
    int tid = threadIdx.x;
    for (int i = tid; i < DDIM * EDIM; i += 256) {
        int d = i >> 4, e = i & 15;
        wgT[e][d] = wg[i];
    }
    __syncthreads();

    int warp = tid >> 5, lane = tid & 31;
    int t = blockIdx.x * 8 + warp;
    const float* xr = x + (size_t)t * DDIM;

    float acc[EDIM];
#pragma unroll
    for (int e = 0; e < EDIM; e++) acc[e] = 0.f;

    for (int d = lane; d < DDIM; d += 32) {
        float xv = xr[d];
#pragma unroll
        for (int e = 0; e < EDIM; e++) acc[e] += xv * wgT[e][d];
    }
#pragma unroll
    for (int e = 0; e < EDIM; e++) {
        acc[e] += __shfl_xor_sync(0xffffffffu, acc[e], 16);
        acc[e] += __shfl_xor_sync(0xffffffffu, acc[e], 8);
        acc[e] += __shfl_xor_sync(0xffffffffu, acc[e], 4);
        acc[e] += __shfl_xor_sync(0xffffffffu, acc[e], 2);
        acc[e] += __shfl_xor_sync(0xffffffffu, acc[e], 1);
    }
    if (lane == 0) {
        float v1 = acc[0]; int i1 = 0;
        float v2 = -3.4e38f; int i2 = 0;
#pragma unroll
        for (int e = 1; e < EDIM; e++) {
            float v = acc[e];
            if (v > v1) { v2 = v1; i2 = i1; v1 = v; i1 = e; }
            else if (v > v2) { v2 = v; i2 = e; }
        }
        float ex  = __expf(v2 - v1);
        float inv = 1.f / (1.f + ex);
        g_eidx[2 * t]     = i1;
        g_eidx[2 * t + 1] = i2;
        g_gw[2 * t]       = inv;
        g_gw[2 * t + 1]   = ex * inv;
        atomicAdd(&g_cnt[i1], 1);
        atomicAdd(&g_cnt[i2], 1);
    }
}

// ---------------- kernel 2: scan + tile plan (single thread; tiny) ----------------
__global__ void plan_kernel() {
    if (threadIdx.x != 0) return;
    int off = 0, nt = 0;
    for (int e = 0; e < EDIM; e++) {
        int n = g_cnt[e];
        g_off[e] = off;
        g_cursor[e] = off;
        int tiles = (n + 127) >> 7;
        for (int r = 0; r < tiles; r++) {
            g_tileE[nt] = e;
            g_tileR[nt] = r << 7;
            nt++;
        }
        off += n;
    }
    g_nTiles = nt;
}

// ---------------- kernel 3: scatter tokens into per-expert lists ----------------
__global__ void scatter_kernel() {
    int t = blockIdx.x * 256 + threadIdx.x;
    int e0 = g_eidx[2 * t];
    int e1 = g_eidx[2 * t + 1];
    int p  = atomicAdd(&g_cursor[e0], 1);
    g_list[p] = 2 * t;
    int p2 = atomicAdd(&g_cursor[e1], 1);
    g_list[p2] = 2 * t + 1;
}

// ---------------- kernel 4: grouped dual GEMM + silu-gate epilogue ----------------
// H[row, :] = gate * silu(x[tok] @ w0[e]) * (x[tok] @ w1[e])
// Tile: BM=128 (rows), BN=64 (per matrix), BK=16, 256 threads, TM=8 x TN=4 per matrix.
__global__ void __launch_bounds__(256, 2)
gemmA_kernel(const float* __restrict__ x,
             const float* __restrict__ w0,
             const float* __restrict__ w1) {
    int tile = blockIdx.y;
    if (tile >= g_nTiles) return;
    const int e       = g_tileE[tile];
    const int rowBase = g_tileR[tile];
    const int off     = g_off[e];
    const int ne      = g_cnt[e];
    const int nb      = blockIdx.x * 64;

    __shared__ __align__(16) float As[2][16][128];
    __shared__ __align__(16) float B0s[2][16][64];
    __shared__ __align__(16) float B1s[2][16][64];

    const int tid = threadIdx.x;

    // A loaders: 2 float4 per thread; idx = u*256+tid; row = idx&127, kvec = idx>>7
    const float* aPtr[2];
    bool aValid[2];
    int aRow[2], aKv[2];
#pragma unroll
    for (int u = 0; u < 2; u++) {
        int idx = u * 256 + tid;
        int ar  = idx & 127;
        int kv  = idx >> 7;
        aRow[u] = ar; aKv[u] = kv;
        int lr  = rowBase + ar;
        bool v  = lr < ne;
        aValid[u] = v;
        int token = 0;
        if (v) token = g_list[off + lr] >> 1;
        aPtr[u] = x + (size_t)token * DDIM + kv * 4;
    }
    // B loaders: 1 float4 per thread per matrix
    const int bk = tid >> 4;
    const int bn = (tid & 15) * 4;
    const float* b0Ptr = w0 + (size_t)e * DDIM * MDIM + (size_t)bk * MDIM + nb + bn;
    const float* b1Ptr = w1 + (size_t)e * DDIM * MDIM + (size_t)bk * MDIM + nb + bn;

    const int ty = tid >> 4;   // 0..15 -> rows ty*8..+7
    const int tx = tid & 15;   // 0..15 -> cols tx*4..+3

    ull acc0[4][4], acc1[4][4];
#pragma unroll
    for (int i = 0; i < 4; i++)
#pragma unroll
        for (int j = 0; j < 4; j++) { acc0[i][j] = 0ull; acc1[i][j] = 0ull; }

    float4 avA[2], bv0, bv1;
    const float4 z4 = make_float4(0.f, 0.f, 0.f, 0.f);

    // prologue: tile 0 -> buffer 0
#pragma unroll
    for (int u = 0; u < 2; u++)
        avA[u] = aValid[u] ? *reinterpret_cast<const float4*>(aPtr[u]) : z4;
    bv0 = *reinterpret_cast<const float4*>(b0Ptr);
    bv1 = *reinterpret_cast<const float4*>(b1Ptr);
#pragma unroll
    for (int u = 0; u < 2; u++) {
        As[0][aKv[u] * 4 + 0][aRow[u]] = avA[u].x;
        As[0][aKv[u] * 4 + 1][aRow[u]] = avA[u].y;
        As[0][aKv[u] * 4 + 2][aRow[u]] = avA[u].z;
        As[0][aKv[u] * 4 + 3][aRow[u]] = avA[u].w;
    }
    *reinterpret_cast<float4*>(&B0s[0][bk][bn]) = bv0;
    *reinterpret_cast<float4*>(&B1s[0][bk][bn]) = bv1;
    __syncthreads();

#define COLA(j, b0c, b1c) do {                              \
        ull d0 = dup2(b0c); ull d1 = dup2(b1c);             \
        acc0[0][j] = fma2(a0, d0, acc0[0][j]);              \
        acc0[1][j] = fma2(a1, d0, acc0[1][j]);              \
        acc0[2][j] = fma2(a2, d0, acc0[2][j]);              \
        acc0[3][j] = fma2(a3, d0, acc0[3][j]);              \
        acc1[0][j] = fma2(a0, d1, acc1[0][j]);              \
        acc1[1][j] = fma2(a1, d1, acc1[1][j]);              \
        acc1[2][j] = fma2(a2, d1, acc1[2][j]);              \
        acc1[3][j] = fma2(a3, d1, acc1[3][j]);              \
    } while (0)

    for (int kt = 0; kt < DDIM / 16; kt++) {
        int cur = kt & 1;
        if (kt < DDIM / 16 - 1) {
#pragma unroll
            for (int u = 0; u < 2; u++)
                avA[u] = aValid[u] ? *reinterpret_cast<const float4*>(aPtr[u] + (kt + 1) * 16) : z4;
            bv0 = *reinterpret_cast<const float4*>(b0Ptr + (size_t)(kt + 1) * 16 * MDIM);
            bv1 = *reinterpret_cast<const float4*>(b1Ptr + (size_t)(kt + 1) * 16 * MDIM);
        }
#pragma unroll
        for (int k = 0; k < 16; k++) {
            const float* arp = &As[cur][k][ty * 8];
            ull a0 = *reinterpret_cast<const ull*>(arp + 0);
            ull a1 = *reinterpret_cast<const ull*>(arp + 2);
            ull a2 = *reinterpret_cast<const ull*>(arp + 4);
            ull a3 = *reinterpret_cast<const ull*>(arp + 6);
            float4 b0 = *reinterpret_cast<const float4*>(&B0s[cur][k][tx * 4]);
            float4 b1 = *reinterpret_cast<const float4*>(&B1s[cur][k][tx * 4]);
            COLA(0, b0.x, b1.x);
            COLA(1, b0.y, b1.y);
            COLA(2, b0.z, b1.z);
            COLA(3, b0.w, b1.w);
        }
        if (kt < DDIM / 16 - 1) {
            int nxt = cur ^ 1;
#pragma unroll
            for (int u = 0; u < 2; u++) {
                As[nxt][aKv[u] * 4 + 0][aRow[u]] = avA[u].x;
                As[nxt][aKv[u] * 4 + 1][aRow[u]] = avA[u].y;
                As[nxt][aKv[u] * 4 + 2][aRow[u]] = avA[u].z;
                As[nxt][aKv[u] * 4 + 3][aRow[u]] = avA[u].w;
            }
            *reinterpret_cast<float4*>(&B0s[nxt][bk][bn]) = bv0;
            *reinterpret_cast<float4*>(&B1s[nxt][bk][bn]) = bv1;
        }
        __syncthreads();
    }
#undef COLA

    // epilogue: h = silu(p) * q * gate, store to g_H (gate folded in here)
#pragma unroll
    for (int i = 0; i < 8; i++) {
        int lr = rowBase + ty * 8 + i;
        if (lr < ne) {
            int entry = g_list[off + lr];
            float g = g_gw[entry];
            float h[4];
#pragma unroll
            for (int j = 0; j < 4; j++) {
                float2 p2 = unpack2(acc0[i >> 1][j]);
                float2 q2 = unpack2(acc1[i >> 1][j]);
                float p = (i & 1) ? p2.y : p2.x;
                float q = (i & 1) ? q2.y : q2.x;
                float s = p / (1.f + __expf(-p));   // silu
                h[j] = s * q * g;
            }
            float4 hv = make_float4(h[0], h[1], h[2], h[3]);
            *reinterpret_cast<float4*>(&g_H[(size_t)(off + lr) * MDIM + nb + tx * 4]) = hv;
        }
    }
}

// ---------------- kernel 5: H @ wo[e], atomic scatter-add into out ----------------
__global__ void __launch_bounds__(256, 2)
gemmB_kernel(const float* __restrict__ wo, float* __restrict__ out) {
    int tile = blockIdx.y;
    if (tile >= g_nTiles) return;
    const int e       = g_tileE[tile];
    const int rowBase = g_tileR[tile];
    const int off     = g_off[e];
    const int ne      = g_cnt[e];
    const int nb      = blockIdx.x * 64;

    __shared__ __align__(16) float As[2][16][128];
    __shared__ __align__(16) float Bs[2][16][64];

    const int tid = threadIdx.x;

    const float* aPtr[2];
    int aRow[2], aKv[2];
#pragma unroll
    for (int u = 0; u < 2; u++) {
        int idx = u * 256 + tid;
        int ar  = idx & 127;
        int kv  = idx >> 7;
        aRow[u] = ar; aKv[u] = kv;
        aPtr[u] = g_H + (size_t)(off + rowBase + ar) * MDIM + kv * 4;  // padded, always in-bounds
    }
    const int bk = tid >> 4;
    const int bn = (tid & 15) * 4;
    const float* bPtr = wo + (size_t)e * MDIM * DDIM + (size_t)bk * DDIM + nb + bn;

    const int ty = tid >> 4;
    const int tx = tid & 15;

    ull acc[4][4];
#pragma unroll
    for (int i = 0; i < 4; i++)
#pragma unroll
        for (int j = 0; j < 4; j++) acc[i][j] = 0ull;

    float4 avA[2], bv;

    // prologue
#pragma unroll
    for (int u = 0; u < 2; u++) avA[u] = *reinterpret_cast<const float4*>(aPtr[u]);
    bv = *reinterpret_cast<const float4*>(bPtr);
#pragma unroll
    for (int u = 0; u < 2; u++) {
        As[0][aKv[u] * 4 + 0][aRow[u]] = avA[u].x;
        As[0][aKv[u] * 4 + 1][aRow[u]] = avA[u].y;
        As[0][aKv[u] * 4 + 2][aRow[u]] = avA[u].z;
        As[0][aKv[u] * 4 + 3][aRow[u]] = avA[u].w;
    }
    *reinterpret_cast<float4*>(&Bs[0][bk][bn]) = bv;
    __syncthreads();

#define COLB(j, bc) do {                                    \
        ull d = dup2(bc);                                   \
        acc[0][j] = fma2(a0, d, acc[0][j]);                 \
        acc[1][j] = fma2(a1, d, acc[1][j]);                 \
        acc[2][j] = fma2(a2, d, acc[2][j]);                 \
        acc[3][j] = fma2(a3, d, acc[3][j]);                 \
    } while (0)

    for (int kt = 0; kt < MDIM / 16; kt++) {
        int cur = kt & 1;
        if (kt < MDIM / 16 - 1) {
#pragma unroll
            for (int u = 0; u < 2; u++)
                avA[u] = *reinterpret_cast<const float4*>(aPtr[u] + (kt + 1) * 16);
            bv = *reinterpret_cast<const float4*>(bPtr + (size_t)(kt + 1) * 16 * DDIM);
        }
#pragma unroll
        for (int k = 0; k < 16; k++) {
            const float* arp = &As[cur][k][ty * 8];
            ull a0 = *reinterpret_cast<const ull*>(arp + 0);
            ull a1 = *reinterpret_cast<const ull*>(arp + 2);
            ull a2 = *reinterpret_cast<const ull*>(arp + 4);
            ull a3 = *reinterpret_cast<const ull*>(arp + 6);
            float4 b = *reinterpret_cast<const float4*>(&Bs[cur][k][tx * 4]);
            COLB(0, b.x);
            COLB(1, b.y);
            COLB(2, b.z);
            COLB(3, b.w);
        }
        if (kt < MDIM / 16 - 1) {
            int nxt = cur ^ 1;
#pragma unroll
            for (int u = 0; u < 2; u++) {
                As[nxt][aKv[u] * 4 + 0][aRow[u]] = avA[u].x;
                As[nxt][aKv[u] * 4 + 1][aRow[u]] = avA[u].y;
                As[nxt][aKv[u] * 4 + 2][aRow[u]] = avA[u].z;
                As[nxt][aKv[u] * 4 + 3][aRow[u]] = avA[u].w;
            }
            *reinterpret_cast<float4*>(&Bs[nxt][bk][bn]) = bv;
        }
        __syncthreads();
    }
#undef COLB

    // epilogue: scatter-add into out (exactly 2 commutative adds per element -> deterministic)
#pragma unroll
    for (int i = 0; i < 8; i++) {
        int lr = rowBase + ty * 8 + i;
        if (lr < ne) {
            int entry = g_list[off + lr];
            int token = entry >> 1;
            float* ob = out + (size_t)token * DDIM + nb + tx * 4;
#pragma unroll
            for (int j = 0; j < 4; j++) {
                float2 c = unpack2(acc[i >> 1][j]);
                atomicAdd(ob + j, (i & 1) ? c.y : c.x);
            }
        }
    }
}

// ---------------- launch ----------------
extern "C" void kernel_launch(void* const* d_in, const int* in_sizes, int n_in,
                              void* d_out, int out_size) {
    const float* x  = (const float*)d_in[0];
    const float* wg = (const float*)d_in[1];
    const float* w0 = (const float*)d_in[2];
    const float* w1 = (const float*)d_in[3];
    const float* wo = (const float*)d_in[4];
    float* out = (float*)d_out;

    cudaMemsetAsync(d_out, 0, (size_t)out_size * sizeof(float), 0);
    init_kernel<<<1, 32>>>();
    routing_kernel<<<T_TOK / 8, 256>>>(x, wg);
    plan_kernel<<<1, 1>>>();
    scatter_kernel<<<T_TOK / 256, 256>>>();
    gemmA_kernel<<<dim3(MDIM / 64, MAXTILES), 256>>>(x, w0, w1);
    gemmB_kernel<<<dim3(DDIM / 64, MAXTILES), 256>>>(wo, out);
}

// round 13
// speedup vs baseline: 1.0001x; 1.0001x over previous
#include <cuda_runtime.h>
#include <cstdint>

// Problem constants
#define T_TOK 32768      // B*S tokens
#define DDIM  512
#define EDIM  16
#define MDIM  1024
#define NROWS (T_TOK * 2)        // total (token,slot) rows = 65536
#define ROWS_PAD (NROWS + 128)
#define MAXTILES 528

typedef unsigned long long ull;

// ---------------- f32x2 packed-math helpers ----------------
__device__ __forceinline__ ull dup2(float v) {
    ull r; unsigned u = __float_as_uint(v);
    asm("mov.b64 %0, {%1, %1};" : "=l"(r) : "r"(u));
    return r;
}
__device__ __forceinline__ ull fma2(ull a, ull b, ull c) {
    ull d;
    asm("fma.rn.f32x2 %0, %1, %2, %3;" : "=l"(d) : "l"(a), "l"(b), "l"(c));
    return d;
}
__device__ __forceinline__ float2 unpack2(ull v) {
    unsigned lo, hi;
    asm("mov.b64 {%0, %1}, %2;" : "=r"(lo), "=r"(hi) : "l"(v));
    return make_float2(__uint_as_float(lo), __uint_as_float(hi));
}

// ---------------- device scratch (allocation-free) ----------------
__device__ float g_H[(size_t)ROWS_PAD * MDIM];   // gated hidden, gate folded in
__device__ int   g_cnt[EDIM];
__device__ int   g_off[EDIM];
__device__ int   g_cursor[EDIM];
__device__ int   g_list[NROWS];                  // packed token*2 + slot, per-expert segments
__device__ float g_gw[NROWS];                    // gate weight, indexed by token*2+slot
__device__ int   g_eidx[NROWS];                  // expert id, indexed by token*2+slot
__device__ int   g_tileE[MAXTILES];
__device__ int   g_tileR[MAXTILES];
__device__ int   g_nTiles;

// ---------------- kernel 0: zero counters ----------------
__global__ void init_kernel() {
    int i = threadIdx.x;
    if (i < EDIM) g_cnt[i] = 0;
}

// ---------------- kernel 1: routing (gate logits + top-2 + softmax) ----------------
__global__ void routing_kernel(const float* __restrict__ x, const float* __restrict__ wg) {
    __shared__ float wgT[EDIM][DDIM];
    int tid = threadIdx.x;
    for (int i = tid; i < DDIM * EDIM; i += 256) {
        int d = i >> 4, e = i & 15;
        wgT[e][d] = wg[i];
    }
    __syncthreads();

    int warp = tid >> 5, lane = tid & 31;
    int t = blockIdx.x * 8 + warp;
    const float* xr = x + (size_t)t * DDIM;

    float acc[EDIM];
#pragma unroll
    for (int e = 0; e < EDIM; e++) acc[e] = 0.f;

    for (int d = lane; d < DDIM; d += 32) {
        float xv = xr[d];
#pragma unroll
        for (int e = 0; e < EDIM; e++) acc[e] += xv * wgT[e][d];
    }
#pragma unroll
    for (int e = 0; e < EDIM; e++) {
        acc[e] += __shfl_xor_sync(0xffffffffu, acc[e], 16);
        acc[e] += __shfl_xor_sync(0xffffffffu, acc[e], 8);
        acc[e] += __shfl_xor_sync(0xffffffffu, acc[e], 4);
        acc[e] += __shfl_xor_sync(0xffffffffu, acc[e], 2);
        acc[e] += __shfl_xor_sync(0xffffffffu, acc[e], 1);
    }
    if (lane == 0) {
        float v1 = acc[0]; int i1 = 0;
        float v2 = -3.4e38f; int i2 = 0;
#pragma unroll
        for (int e = 1; e < EDIM; e++) {
            float v = acc[e];
            if (v > v1) { v2 = v1; i2 = i1; v1 = v; i1 = e; }
            else if (v > v2) { v2 = v; i2 = e; }
        }
        float ex  = __expf(v2 - v1);
        float inv = 1.f / (1.f + ex);
        g_eidx[2 * t]     = i1;
        g_eidx[2 * t + 1] = i2;
        g_gw[2 * t]       = inv;
        g_gw[2 * t + 1]   = ex * inv;
        atomicAdd(&g_cnt[i1], 1);
        atomicAdd(&g_cnt[i2], 1);
    }
}

// ---------------- kernel 2: scan + tile plan (single thread; tiny) ----------------
__global__ void plan_kernel() {
    if (threadIdx.x != 0) return;
    int off = 0, nt = 0;
    for (int e = 0; e < EDIM; e++) {
        int n = g_cnt[e];
        g_off[e] = off;
        g_cursor[e] = off;
        int tiles = (n + 127) >> 7;
        for (int r = 0; r < tiles; r++) {
            g_tileE[nt] = e;
            g_tileR[nt] = r << 7;
            nt++;
        }
        off += n;
    }
    g_nTiles = nt;
}

// ---------------- kernel 3: scatter tokens into per-expert lists ----------------
__global__ void scatter_kernel() {
    int t = blockIdx.x * 256 + threadIdx.x;
    int e0 = g_eidx[2 * t];
    int e1 = g_eidx[2 * t + 1];
    int p  = atomicAdd(&g_cursor[e0], 1);
    g_list[p] = 2 * t;
    int p2 = atomicAdd(&g_cursor[e1], 1);
    g_list[p2] = 2 * t + 1;
}

// ---------------- kernel 4: grouped dual GEMM + silu-gate epilogue ----------------
// H[row, :] = gate * silu(x[tok] @ w0[e]) * (x[tok] @ w1[e])
// Tile: BM=128 (rows), BN=64 (per matrix), BK=16, 256 threads, TM=8 x TN=4 per matrix.
__global__ void __launch_bounds__(256, 2)
gemmA_kernel(const float* __restrict__ x,
             const float* __restrict__ w0,
             const float* __restrict__ w1) {
    int tile = blockIdx.y;
    if (tile >= g_nTiles) return;
    const int e       = g_tileE[tile];
    const int rowBase = g_tileR[tile];
    const int off     = g_off[e];
    const int ne      = g_cnt[e];
    const int nb      = blockIdx.x * 64;

    __shared__ __align__(16) float As[2][16][128];
    __shared__ __align__(16) float B0s[2][16][64];
    __shared__ __align__(16) float B1s[2][16][64];

    const int tid = threadIdx.x;

    // A loaders: 2 float4 per thread; idx = u*256+tid; row = idx&127, kvec = idx>>7
    const float* aPtr[2];
    bool aValid[2];
    int aRow[2], aKv[2];
#pragma unroll
    for (int u = 0; u < 2; u++) {
        int idx = u * 256 + tid;
        int ar  = idx & 127;
        int kv  = idx >> 7;
        aRow[u] = ar; aKv[u] = kv;
        int lr  = rowBase + ar;
        bool v  = lr < ne;
        aValid[u] = v;
        int token = 0;
        if (v) token = g_list[off + lr] >> 1;
        aPtr[u] = x + (size_t)token * DDIM + kv * 4;
    }
    // B loaders: 1 float4 per thread per matrix
    const int bk = tid >> 4;
    const int bn = (tid & 15) * 4;
    const float* b0Ptr = w0 + (size_t)e * DDIM * MDIM + (size_t)bk * MDIM + nb + bn;
    const float* b1Ptr = w1 + (size_t)e * DDIM * MDIM + (size_t)bk * MDIM + nb + bn;

    const int ty = tid >> 4;   // 0..15 -> rows ty*8..+7
    const int tx = tid & 15;   // 0..15 -> cols tx*4..+3

    ull acc0[4][4], acc1[4][4];
#pragma unroll
    for (int i = 0; i < 4; i++)
#pragma unroll
        for (int j = 0; j < 4; j++) { acc0[i][j] = 0ull; acc1[i][j] = 0ull; }

    float4 avA[2], bv0, bv1;
    const float4 z4 = make_float4(0.f, 0.f, 0.f, 0.f);

    // prologue: tile 0 -> buffer 0
#pragma unroll
    for (int u = 0; u < 2; u++)
        avA[u] = aValid[u] ? *reinterpret_cast<const float4*>(aPtr[u]) : z4;
    bv0 = *reinterpret_cast<const float4*>(b0Ptr);
    bv1 = *reinterpret_cast<const float4*>(b1Ptr);
#pragma unroll
    for (int u = 0; u < 2; u++) {
        As[0][aKv[u] * 4 + 0][aRow[u]] = avA[u].x;
        As[0][aKv[u] * 4 + 1][aRow[u]] = avA[u].y;
        As[0][aKv[u] * 4 + 2][aRow[u]] = avA[u].z;
        As[0][aKv[u] * 4 + 3][aRow[u]] = avA[u].w;
    }
    *reinterpret_cast<float4*>(&B0s[0][bk][bn]) = bv0;
    *reinterpret_cast<float4*>(&B1s[0][bk][bn]) = bv1;
    __syncthreads();

#define COLA(j, b0c, b1c) do {                              \
        ull d0 = dup2(b0c); ull d1 = dup2(b1c);             \
        acc0[0][j] = fma2(a0, d0, acc0[0][j]);              \
        acc0[1][j] = fma2(a1, d0, acc0[1][j]);              \
        acc0[2][j] = fma2(a2, d0, acc0[2][j]);              \
        acc0[3][j] = fma2(a3, d0, acc0[3][j]);              \
        acc1[0][j] = fma2(a0, d1, acc1[0][j]);              \
        acc1[1][j] = fma2(a1, d1, acc1[1][j]);              \
        acc1[2][j] = fma2(a2, d1, acc1[2][j]);              \
        acc1[3][j] = fma2(a3, d1, acc1[3][j]);              \
    } while (0)

    for (int kt = 0; kt < DDIM / 16; kt++) {
        int cur = kt & 1;
        if (kt < DDIM / 16 - 1) {
#pragma unroll
            for (int u = 0; u < 2; u++)
                avA[u] = aValid[u] ? *reinterpret_cast<const float4*>(aPtr[u] + (kt + 1) * 16) : z4;
            bv0 = *reinterpret_cast<const float4*>(b0Ptr + (size_t)(kt + 1) * 16 * MDIM);
            bv1 = *reinterpret_cast<const float4*>(b1Ptr + (size_t)(kt + 1) * 16 * MDIM);
        }
#pragma unroll
        for (int k = 0; k < 16; k++) {
            const float* arp = &As[cur][k][ty * 8];
            ull a0 = *reinterpret_cast<const ull*>(arp + 0);
            ull a1 = *reinterpret_cast<const ull*>(arp + 2);
            ull a2 = *reinterpret_cast<const ull*>(arp + 4);
            ull a3 = *reinterpret_cast<const ull*>(arp + 6);
            float4 b0 = *reinterpret_cast<const float4*>(&B0s[cur][k][tx * 4]);
            float4 b1 = *reinterpret_cast<const float4*>(&B1s[cur][k][tx * 4]);
            COLA(0, b0.x, b1.x);
            COLA(1, b0.y, b1.y);
            COLA(2, b0.z, b1.z);
            COLA(3, b0.w, b1.w);
        }
        if (kt < DDIM / 16 - 1) {
            int nxt = cur ^ 1;
#pragma unroll
            for (int u = 0; u < 2; u++) {
                As[nxt][aKv[u] * 4 + 0][aRow[u]] = avA[u].x;
                As[nxt][aKv[u] * 4 + 1][aRow[u]] = avA[u].y;
                As[nxt][aKv[u] * 4 + 2][aRow[u]] = avA[u].z;
                As[nxt][aKv[u] * 4 + 3][aRow[u]] = avA[u].w;
            }
            *reinterpret_cast<float4*>(&B0s[nxt][bk][bn]) = bv0;
            *reinterpret_cast<float4*>(&B1s[nxt][bk][bn]) = bv1;
        }
        __syncthreads();
    }
#undef COLA

    // epilogue: h = silu(p) * q * gate, store to g_H (gate folded in here)
#pragma unroll
    for (int i = 0; i < 8; i++) {
        int lr = rowBase + ty * 8 + i;
        if (lr < ne) {
            int entry = g_list[off + lr];
            float g = g_gw[entry];
            float h[4];
#pragma unroll
            for (int j = 0; j < 4; j++) {
                float2 p2 = unpack2(acc0[i >> 1][j]);
                float2 q2 = unpack2(acc1[i >> 1][j]);
                float p = (i & 1) ? p2.y : p2.x;
                float q = (i & 1) ? q2.y : q2.x;
                float s = p / (1.f + __expf(-p));   // silu
                h[j] = s * q * g;
            }
            float4 hv = make_float4(h[0], h[1], h[2], h[3]);
            *reinterpret_cast<float4*>(&g_H[(size_t)(off + lr) * MDIM + nb + tx * 4]) = hv;
        }
    }
}

// ---------------- kernel 5: H @ wo[e], atomic scatter-add into out ----------------
__global__ void __launch_bounds__(256, 2)
gemmB_kernel(const float* __restrict__ wo, float* __restrict__ out) {
    int tile = blockIdx.y;
    if (tile >= g_nTiles) return;
    const int e       = g_tileE[tile];
    const int rowBase = g_tileR[tile];
    const int off     = g_off[e];
    const int ne      = g_cnt[e];
    const int nb      = blockIdx.x * 64;

    __shared__ __align__(16) float As[2][16][128];
    __shared__ __align__(16) float Bs[2][16][64];

    const int tid = threadIdx.x;

    const float* aPtr[2];
    int aRow[2], aKv[2];
#pragma unroll
    for (int u = 0; u < 2; u++) {
        int idx = u * 256 + tid;
        int ar  = idx & 127;
        int kv  = idx >> 7;
        aRow[u] = ar; aKv[u] = kv;
        aPtr[u] = g_H + (size_t)(off + rowBase + ar) * MDIM + kv * 4;  // padded, always in-bounds
    }
    const int bk = tid >> 4;
    const int bn = (tid & 15) * 4;
    const float* bPtr = wo + (size_t)e * MDIM * DDIM + (size_t)bk * DDIM + nb + bn;

    const int ty = tid >> 4;
    const int tx = tid & 15;

    ull acc[4][4];
#pragma unroll
    for (int i = 0; i < 4; i++)
#pragma unroll
        for (int j = 0; j < 4; j++) acc[i][j] = 0ull;

    float4 avA[2], bv;

    // prologue
#pragma unroll
    for (int u = 0; u < 2; u++) avA[u] = *reinterpret_cast<const float4*>(aPtr[u]);
    bv = *reinterpret_cast<const float4*>(bPtr);
#pragma unroll
    for (int u = 0; u < 2; u++) {
        As[0][aKv[u] * 4 + 0][aRow[u]] = avA[u].x;
        As[0][aKv[u] * 4 + 1][aRow[u]] = avA[u].y;
        As[0][aKv[u] * 4 + 2][aRow[u]] = avA[u].z;
        As[0][aKv[u] * 4 + 3][aRow[u]] = avA[u].w;
    }
    *reinterpret_cast<float4*>(&Bs[0][bk][bn]) = bv;
    __syncthreads();

#define COLB(j, bc) do {                                    \
        ull d = dup2(bc);                                   \
        acc[0][j] = fma2(a0, d, acc[0][j]);                 \
        acc[1][j] = fma2(a1, d, acc[1][j]);                 \
        acc[2][j] = fma2(a2, d, acc[2][j]);                 \
        acc[3][j] = fma2(a3, d, acc[3][j]);                 \
    } while (0)

    for (int kt = 0; kt < MDIM / 16; kt++) {
        int cur = kt & 1;
        if (kt < MDIM / 16 - 1) {
#pragma unroll
            for (int u = 0; u < 2; u++)
                avA[u] = *reinterpret_cast<const float4*>(aPtr[u] + (kt + 1) * 16);
            bv = *reinterpret_cast<const float4*>(bPtr + (size_t)(kt + 1) * 16 * DDIM);
        }
#pragma unroll
        for (int k = 0; k < 16; k++) {
            const float* arp = &As[cur][k][ty * 8];
            ull a0 = *reinterpret_cast<const ull*>(arp + 0);
            ull a1 = *reinterpret_cast<const ull*>(arp + 2);
            ull a2 = *reinterpret_cast<const ull*>(arp + 4);
            ull a3 = *reinterpret_cast<const ull*>(arp + 6);
            float4 b = *reinterpret_cast<const float4*>(&Bs[cur][k][tx * 4]);
            COLB(0, b.x);
            COLB(1, b.y);
            COLB(2, b.z);
            COLB(3, b.w);
        }
        if (kt < MDIM / 16 - 1) {
            int nxt = cur ^ 1;
#pragma unroll
            for (int u = 0; u < 2; u++) {
                As[nxt][aKv[u] * 4 + 0][aRow[u]] = avA[u].x;
                As[nxt][aKv[u] * 4 + 1][aRow[u]] = avA[u].y;
                As[nxt][aKv[u] * 4 + 2][aRow[u]] = avA[u].z;
                As[nxt][aKv[u] * 4 + 3][aRow[u]] = avA[u].w;
            }
            *reinterpret_cast<float4*>(&Bs[nxt][bk][bn]) = bv;
        }
        __syncthreads();
    }
#undef COLB

    // epilogue: scatter-add into out (exactly 2 commutative adds per element -> deterministic)
#pragma unroll
    for (int i = 0; i < 8; i++) {
        int lr = rowBase + ty * 8 + i;
        if (lr < ne) {
            int entry = g_list[off + lr];
            int token = entry >> 1;
            float* ob = out + (size_t)token * DDIM + nb + tx * 4;
#pragma unroll
            for (int j = 0; j < 4; j++) {
                float2 c = unpack2(acc[i >> 1][j]);
                atomicAdd(ob + j, (i & 1) ? c.y : c.x);
            }
        }
    }
}

// ---------------- launch ----------------
extern "C" void kernel_launch(void* const* d_in, const int* in_sizes, int n_in,
                              void* d_out, int out_size) {
    const float* x  = (const float*)d_in[0];
    const float* wg = (const float*)d_in[1];
    const float* w0 = (const float*)d_in[2];
    const float* w1 = (const float*)d_in[3];
    const float* wo = (const float*)d_in[4];
    float* out = (float*)d_out;

    cudaMemsetAsync(d_out, 0, (size_t)out_size * sizeof(float), 0);
    init_kernel<<<1, 32>>>();
    routing_kernel<<<T_TOK / 8, 256>>>(x, wg);
    plan_kernel<<<1, 1>>>();
    scatter_kernel<<<T_TOK / 256, 256>>>();
    gemmA_kernel<<<dim3(MDIM / 64, MAXTILES), 256>>>(x, w0, w1);
    gemmB_kernel<<<dim3(DDIM / 64, MAXTILES), 256>>>(wo, out);
}

// round 14
// speedup vs baseline: 1.0002x; 1.0000x over previous
#include <cuda_runtime.h>
#include <cstdint>

// Problem constants
#define T_TOK 32768      // B*S tokens
#define DDIM  512
#define EDIM  16
#define MDIM  1024
#define NROWS (T_TOK * 2)        // total (token,slot) rows = 65536
#define ROWS_PAD (NROWS + 128)
#define MAXTILES 528

typedef unsigned long long ull;

// ---------------- f32x2 packed-math helpers ----------------
__device__ __forceinline__ ull dup2(float v) {
    ull r; unsigned u = __float_as_uint(v);
    asm("mov.b64 %0, {%1, %1};" : "=l"(r) : "r"(u));
    return r;
}
__device__ __forceinline__ ull fma2(ull a, ull b, ull c) {
    ull d;
    asm("fma.rn.f32x2 %0, %1, %2, %3;" : "=l"(d) : "l"(a), "l"(b), "l"(c));
    return d;
}
__device__ __forceinline__ float2 unpack2(ull v) {
    unsigned lo, hi;
    asm("mov.b64 {%0, %1}, %2;" : "=r"(lo), "=r"(hi) : "l"(v));
    return make_float2(__uint_as_float(lo), __uint_as_float(hi));
}

// ---------------- device scratch (allocation-free) ----------------
__device__ float g_H[(size_t)ROWS_PAD * MDIM];   // gated hidden, gate folded in
__device__ int   g_cnt[EDIM];
__device__ int   g_off[EDIM];
__device__ int   g_cursor[EDIM];
__device__ int   g_list[NROWS];                  // packed token*2 + slot, per-expert segments
__device__ float g_gw[NROWS];                    // gate weight, indexed by token*2+slot
__device__ int   g_eidx[NROWS];                  // expert id, indexed by token*2+slot
__device__ int   g_tileE[MAXTILES];
__device__ int   g_tileR[MAXTILES];
__device__ int   g_nTiles;

// ---------------- kernel 0: zero counters ----------------
__global__ void init_kernel() {
    int i = threadIdx.x;
    if (i < EDIM) g_cnt[i] = 0;
}

// ---------------- kernel 1: routing (gate logits + top-2 + softmax) ----------------
__global__ void routing_kernel(const float* __restrict__ x, const float* __restrict__ wg) {
    __shared__ float wgT[EDIM][DDIM];
    int tid = threadIdx.x;
    for (int i = tid; i < DDIM * EDIM; i += 256) {
        int d = i >> 4, e = i & 15;
        wgT[e][d] = wg[i];
    }
    __syncthreads();

    int warp = tid >> 5, lane = tid & 31;
    int t = blockIdx.x * 8 + warp;
    const float* xr = x + (size_t)t * DDIM;

    float acc[EDIM];
#pragma unroll
    for (int e = 0; e < EDIM; e++) acc[e] = 0.f;

    for (int d = lane; d < DDIM; d += 32) {
        float xv = xr[d];
#pragma unroll
        for (int e = 0; e < EDIM; e++) acc[e] += xv * wgT[e][d];
    }
#pragma unroll
    for (int e = 0; e < EDIM; e++) {
        acc[e] += __shfl_xor_sync(0xffffffffu, acc[e], 16);
        acc[e] += __shfl_xor_sync(0xffffffffu, acc[e], 8);
        acc[e] += __shfl_xor_sync(0xffffffffu, acc[e], 4);
        acc[e] += __shfl_xor_sync(0xffffffffu, acc[e], 2);
        acc[e] += __shfl_xor_sync(0xffffffffu, acc[e], 1);
    }
    if (lane == 0) {
        float v1 = acc[0]; int i1 = 0;
        float v2 = -3.4e38f; int i2 = 0;
#pragma unroll
        for (int e = 1; e < EDIM; e++) {
            float v = acc[e];
            if (v > v1) { v2 = v1; i2 = i1; v1 = v; i1 = e; }
            else if (v > v2) { v2 = v; i2 = e; }
        }
        float ex  = __expf(v2 - v1);
        float inv = 1.f / (1.f + ex);
        g_eidx[2 * t]     = i1;
        g_eidx[2 * t + 1] = i2;
        g_gw[2 * t]       = inv;
        g_gw[2 * t + 1]   = ex * inv;
        atomicAdd(&g_cnt[i1], 1);
        atomicAdd(&g_cnt[i2], 1);
    }
}

// ---------------- kernel 2: scan + tile plan (single thread; tiny) ----------------
__global__ void plan_kernel() {
    if (threadIdx.x != 0) return;
    int off = 0, nt = 0;
    for (int e = 0; e < EDIM; e++) {
        int n = g_cnt[e];
        g_off[e] = off;
        g_cursor[e] = off;
        int tiles = (n + 127) >> 7;
        for (int r = 0; r < tiles; r++) {
            g_tileE[nt] = e;
            g_tileR[nt] = r << 7;
            nt++;
        }
        off += n;
    }
    g_nTiles = nt;
}

// ---------------- kernel 3: scatter tokens into per-expert lists ----------------
__global__ void scatter_kernel() {
    int t = blockIdx.x * 256 + threadIdx.x;
    int e0 = g_eidx[2 * t];
    int e1 = g_eidx[2 * t + 1];
    int p  = atomicAdd(&g_cursor[e0], 1);
    g_list[p] = 2 * t;
    int p2 = atomicAdd(&g_cursor[e1], 1);
    g_list[p2] = 2 * t + 1;
}

// ---------------- kernel 4: grouped dual GEMM + silu-gate epilogue ----------------
// H[row, :] = gate * silu(x[tok] @ w0[e]) * (x[tok] @ w1[e])
// Tile: BM=128 (rows), BN=64 (per matrix), BK=16, 256 threads, TM=8 x TN=4 per matrix.
__global__ void __launch_bounds__(256, 2)
gemmA_kernel(const float* __restrict__ x,
             const float* __restrict__ w0,
             const float* __restrict__ w1) {
    int tile = blockIdx.y;
    if (tile >= g_nTiles) return;
    const int e       = g_tileE[tile];
    const int rowBase = g_tileR[tile];
    const int off     = g_off[e];
    const int ne      = g_cnt[e];
    const int nb      = blockIdx.x * 64;

    __shared__ __align__(16) float As[2][16][128];
    __shared__ __align__(16) float B0s[2][16][64];
    __shared__ __align__(16) float B1s[2][16][64];

    const int tid = threadIdx.x;

    // A loaders: 2 float4 per thread; idx = u*256+tid; row = idx&127, kvec = idx>>7
    const float* aPtr[2];
    bool aValid[2];
    int aRow[2], aKv[2];
#pragma unroll
    for (int u = 0; u < 2; u++) {
        int idx = u * 256 + tid;
        int ar  = idx & 127;
        int kv  = idx >> 7;
        aRow[u] = ar; aKv[u] = kv;
        int lr  = rowBase + ar;
        bool v  = lr < ne;
        aValid[u] = v;
        int token = 0;
        if (v) token = g_list[off + lr] >> 1;
        aPtr[u] = x + (size_t)token * DDIM + kv * 4;
    }
    // B loaders: 1 float4 per thread per matrix
    const int bk = tid >> 4;
    const int bn = (tid & 15) * 4;
    const float* b0Ptr = w0 + (size_t)e * DDIM * MDIM + (size_t)bk * MDIM + nb + bn;
    const float* b1Ptr = w1 + (size_t)e * DDIM * MDIM + (size_t)bk * MDIM + nb + bn;

    const int ty = tid >> 4;   // 0..15 -> rows ty*8..+7
    const int tx = tid & 15;   // 0..15 -> cols tx*4..+3

    ull acc0[4][4], acc1[4][4];
#pragma unroll
    for (int i = 0; i < 4; i++)
#pragma unroll
        for (int j = 0; j < 4; j++) { acc0[i][j] = 0ull; acc1[i][j] = 0ull; }

    float4 avA[2], bv0, bv1;
    const float4 z4 = make_float4(0.f, 0.f, 0.f, 0.f);

    // prologue: tile 0 -> buffer 0
#pragma unroll
    for (int u = 0; u < 2; u++)
        avA[u] = aValid[u] ? *reinterpret_cast<const float4*>(aPtr[u]) : z4;
    bv0 = *reinterpret_cast<const float4*>(b0Ptr);
    bv1 = *reinterpret_cast<const float4*>(b1Ptr);
#pragma unroll
    for (int u = 0; u < 2; u++) {
        As[0][aKv[u] * 4 + 0][aRow[u]] = avA[u].x;
        As[0][aKv[u] * 4 + 1][aRow[u]] = avA[u].y;
        As[0][aKv[u] * 4 + 2][aRow[u]] = avA[u].z;
        As[0][aKv[u] * 4 + 3][aRow[u]] = avA[u].w;
    }
    *reinterpret_cast<float4*>(&B0s[0][bk][bn]) = bv0;
    *reinterpret_cast<float4*>(&B1s[0][bk][bn]) = bv1;
    __syncthreads();

#define COLA(j, b0c, b1c) do {                              \
        ull d0 = dup2(b0c); ull d1 = dup2(b1c);             \
        acc0[0][j] = fma2(a0, d0, acc0[0][j]);              \
        acc0[1][j] = fma2(a1, d0, acc0[1][j]);              \
        acc0[2][j] = fma2(a2, d0, acc0[2][j]);              \
        acc0[3][j] = fma2(a3, d0, acc0[3][j]);              \
        acc1[0][j] = fma2(a0, d1, acc1[0][j]);              \
        acc1[1][j] = fma2(a1, d1, acc1[1][j]);              \
        acc1[2][j] = fma2(a2, d1, acc1[2][j]);              \
        acc1[3][j] = fma2(a3, d1, acc1[3][j]);              \
    } while (0)

    for (int kt = 0; kt < DDIM / 16; kt++) {
        int cur = kt & 1;
        if (kt < DDIM / 16 - 1) {
#pragma unroll
            for (int u = 0; u < 2; u++)
                avA[u] = aValid[u] ? *reinterpret_cast<const float4*>(aPtr[u] + (kt + 1) * 16) : z4;
            bv0 = *reinterpret_cast<const float4*>(b0Ptr + (size_t)(kt + 1) * 16 * MDIM);
            bv1 = *reinterpret_cast<const float4*>(b1Ptr + (size_t)(kt + 1) * 16 * MDIM);
        }
#pragma unroll
        for (int k = 0; k < 16; k++) {
            const float* arp = &As[cur][k][ty * 8];
            ull a0 = *reinterpret_cast<const ull*>(arp + 0);
            ull a1 = *reinterpret_cast<const ull*>(arp + 2);
            ull a2 = *reinterpret_cast<const ull*>(arp + 4);
            ull a3 = *reinterpret_cast<const ull*>(arp + 6);
            float4 b0 = *reinterpret_cast<const float4*>(&B0s[cur][k][tx * 4]);
            float4 b1 = *reinterpret_cast<const float4*>(&B1s[cur][k][tx * 4]);
            COLA(0, b0.x, b1.x);
            COLA(1, b0.y, b1.y);
            COLA(2, b0.z, b1.z);
            COLA(3, b0.w, b1.w);
        }
        if (kt < DDIM / 16 - 1) {
            int nxt = cur ^ 1;
#pragma unroll
            for (int u = 0; u < 2; u++) {
                As[nxt][aKv[u] * 4 + 0][aRow[u]] = avA[u].x;
                As[nxt][aKv[u] * 4 + 1][aRow[u]] = avA[u].y;
                As[nxt][aKv[u] * 4 + 2][aRow[u]] = avA[u].z;
                As[nxt][aKv[u] * 4 + 3][aRow[u]] = avA[u].w;
            }
            *reinterpret_cast<float4*>(&B0s[nxt][bk][bn]) = bv0;
            *reinterpret_cast<float4*>(&B1s[nxt][bk][bn]) = bv1;
        }
        __syncthreads();
    }
#undef COLA

    // epilogue: h = silu(p) * q * gate, store to g_H (gate folded in here)
#pragma unroll
    for (int i = 0; i < 8; i++) {
        int lr = rowBase + ty * 8 + i;
        if (lr < ne) {
            int entry = g_list[off + lr];
            float g = g_gw[entry];
            float h[4];
#pragma unroll
            for (int j = 0; j < 4; j++) {
                float2 p2 = unpack2(acc0[i >> 1][j]);
                float2 q2 = unpack2(acc1[i >> 1][j]);
                float p = (i & 1) ? p2.y : p2.x;
                float q = (i & 1) ? q2.y : q2.x;
                float s = p / (1.f + __expf(-p));   // silu
                h[j] = s * q * g;
            }
            float4 hv = make_float4(h[0], h[1], h[2], h[3]);
            *reinterpret_cast<float4*>(&g_H[(size_t)(off + lr) * MDIM + nb + tx * 4]) = hv;
        }
    }
}

// ---------------- kernel 5: H @ wo[e], atomic scatter-add into out ----------------
__global__ void __launch_bounds__(256, 2)
gemmB_kernel(const float* __restrict__ wo, float* __restrict__ out) {
    int tile = blockIdx.y;
    if (tile >= g_nTiles) return;
    const int e       = g_tileE[tile];
    const int rowBase = g_tileR[tile];
    const int off     = g_off[e];
    const int ne      = g_cnt[e];
    const int nb      = blockIdx.x * 64;

    __shared__ __align__(16) float As[2][16][128];
    __shared__ __align__(16) float Bs[2][16][64];

    const int tid = threadIdx.x;

    const float* aPtr[2];
    int aRow[2], aKv[2];
#pragma unroll
    for (int u = 0; u < 2; u++) {
        int idx = u * 256 + tid;
        int ar  = idx & 127;
        int kv  = idx >> 7;
        aRow[u] = ar; aKv[u] = kv;
        aPtr[u] = g_H + (size_t)(off + rowBase + ar) * MDIM + kv * 4;  // padded, always in-bounds
    }
    const int bk = tid >> 4;
    const int bn = (tid & 15) * 4;
    const float* bPtr = wo + (size_t)e * MDIM * DDIM + (size_t)bk * DDIM + nb + bn;

    const int ty = tid >> 4;
    const int tx = tid & 15;

    ull acc[4][4];
#pragma unroll
    for (int i = 0; i < 4; i++)
#pragma unroll
        for (int j = 0; j < 4; j++) acc[i][j] = 0ull;

    float4 avA[2], bv;

    // prologue
#pragma unroll
    for (int u = 0; u < 2; u++) avA[u] = *reinterpret_cast<const float4*>(aPtr[u]);
    bv = *reinterpret_cast<const float4*>(bPtr);
#pragma unroll
    for (int u = 0; u < 2; u++) {
        As[0][aKv[u] * 4 + 0][aRow[u]] = avA[u].x;
        As[0][aKv[u] * 4 + 1][aRow[u]] = avA[u].y;
        As[0][aKv[u] * 4 + 2][aRow[u]] = avA[u].z;
        As[0][aKv[u] * 4 + 3][aRow[u]] = avA[u].w;
    }
    *reinterpret_cast<float4*>(&Bs[0][bk][bn]) = bv;
    __syncthreads();

#define COLB(j, bc) do {                                    \
        ull d = dup2(bc);                                   \
        acc[0][j] = fma2(a0, d, acc[0][j]);                 \
        acc[1][j] = fma2(a1, d, acc[1][j]);                 \
        acc[2][j] = fma2(a2, d, acc[2][j]);                 \
        acc[3][j] = fma2(a3, d, acc[3][j]);                 \
    } while (0)

    for (int kt = 0; kt < MDIM / 16; kt++) {
        int cur = kt & 1;
        if (kt < MDIM / 16 - 1) {
#pragma unroll
            for (int u = 0; u < 2; u++)
                avA[u] = *reinterpret_cast<const float4*>(aPtr[u] + (kt + 1) * 16);
            bv = *reinterpret_cast<const float4*>(bPtr + (size_t)(kt + 1) * 16 * DDIM);
        }
#pragma unroll
        for (int k = 0; k < 16; k++) {
            const float* arp = &As[cur][k][ty * 8];
            ull a0 = *reinterpret_cast<const ull*>(arp + 0);
            ull a1 = *reinterpret_cast<const ull*>(arp + 2);
            ull a2 = *reinterpret_cast<const ull*>(arp + 4);
            ull a3 = *reinterpret_cast<const ull*>(arp + 6);
            float4 b = *reinterpret_cast<const float4*>(&Bs[cur][k][tx * 4]);
            COLB(0, b.x);
            COLB(1, b.y);
            COLB(2, b.z);
            COLB(3, b.w);
        }
        if (kt < MDIM / 16 - 1) {
            int nxt = cur ^ 1;
#pragma unroll
            for (int u = 0; u < 2; u++) {
                As[nxt][aKv[u] * 4 + 0][aRow[u]] = avA[u].x;
                As[nxt][aKv[u] * 4 + 1][aRow[u]] = avA[u].y;
                As[nxt][aKv[u] * 4 + 2][aRow[u]] = avA[u].z;
                As[nxt][aKv[u] * 4 + 3][aRow[u]] = avA[u].w;
            }
            *reinterpret_cast<float4*>(&Bs[nxt][bk][bn]) = bv;
        }
        __syncthreads();
    }
#undef COLB

    // epilogue: scatter-add into out (exactly 2 commutative adds per element -> deterministic)
#pragma unroll
    for (int i = 0; i < 8; i++) {
        int lr = rowBase + ty * 8 + i;
        if (lr < ne) {
            int entry = g_list[off + lr];
            int token = entry >> 1;
            float* ob = out + (size_t)token * DDIM + nb + tx * 4;
#pragma unroll
            for (int j = 0; j < 4; j++) {
                float2 c = unpack2(acc[i >> 1][j]);
                atomicAdd(ob + j, (i & 1) ? c.y : c.x);
            }
        }
    }
}

// ---------------- launch ----------------
extern "C" void kernel_launch(void* const* d_in, const int* in_sizes, int n_in,
                              void* d_out, int out_size) {
    const float* x  = (const float*)d_in[0];
    const float* wg = (const float*)d_in[1];
    const float* w0 = (const float*)d_in[2];
    const float* w1 = (const float*)d_in[3];
    const float* wo = (const float*)d_in[4];
    float* out = (float*)d_out;

    cudaMemsetAsync(d_out, 0, (size_t)out_size * sizeof(float), 0);
    init_kernel<<<1, 32>>>();
    routing_kernel<<<T_TOK / 8, 256>>>(x, wg);
    plan_kernel<<<1, 1>>>();
    scatter_kernel<<<T_TOK / 256, 256>>>();
    gemmA_kernel<<<dim3(MDIM / 64, MAXTILES), 256>>>(x, w0, w1);
    gemmB_kernel<<<dim3(DDIM / 64, MAXTILES), 256>>>(wo, out);
}